// round 14
// baseline (speedup 1.0000x reference)
#include <cuda_runtime.h>
#include <cstdint>

#define KS 93          // gaussian kernel size (static, matches reference)
#define NPTS 256       // points per batch
#define W_OUT 512
#define H_OUT 512
#define RPB 8          // rows per warp tile
#define NT 256         // 8 warps per block; warp w -> 64-col window
#define P 64           // gaussian table base: index for patch offset 0
#define GLEN 220       // table length: nonzero exactly in [P, P+93)

// One block per (batch, 8-row group): grid = 8*64 = 512, 8 warps each.
// Warp w owns cols [64w, 64w+64); lane owns 2 adjacent columns.
// Each warp classifies all 256 points itself -> warp-private compact list
// holding pre-baked smem byte offsets. 2 barriers total (table build).
__global__ __launch_bounds__(NT)
void density_kernel(const float* __restrict__ labels,
                    const float* __restrict__ sigma_ptr,
                    float* __restrict__ out) {
    const int rowBase = (blockIdx.x & 63) * RPB;
    const int b       = blockIdx.x >> 6;
    const int t    = threadIdx.x;
    const int warp = t >> 5;
    const int lane = t & 31;
    const int cbw  = warp * 64;                   // this warp's column base

    __shared__ __align__(16) float4 gquad[GLEN];  // {T[i],T[i],T[i+1],T[i+1]}
    __shared__ __align__(8)  float2 gpair[GLEN];  // {T[i], T[i+1]}
    __shared__ int   lists[8][NPTS];              // warp-private compact lists
    __shared__ float wsum[3];

    // ---- Kick off global loads (4 labels per lane + sigma) ---------------
    const float2* lab = (const float2*)(labels + (size_t)b * NPTS * 2);
    float2 pt[8];
    #pragma unroll
    for (int r = 0; r < 8; r++) pt[r] = lab[r * 32 + lane];
    const float s = fabsf(sigma_ptr[0]);
    const float inv2s2 = 1.0f / (2.0f * s * s);

    // ---- Warp-local classification (pre-barrier; overlaps LDG latency) ---
    // da7  = rowBase - R0 + 7  in [0, 99]  <-> row window hit
    // dc63 = cbw    - C0 + 63 in [0, 155] <-> col window hit
    // entry packs byte offsets: (quad byte off << 16) | pair byte off
    int  pk[8];
    bool av[8];
    #pragma unroll
    for (int r = 0; r < 8; r++) {
        const int da7  = rowBase - (int)truncf(pt[r].x - 46.5f) + 7;
        const int dc63 = cbw     - (int)truncf(pt[r].y - 46.5f) + 63;
        pk[r] = (((57 + da7) << 4) << 16) | ((1 + dc63) << 3);
        av[r] = ((unsigned)da7  < (unsigned)(KS + RPB - 1)) &&
                ((unsigned)dc63 < (unsigned)(KS + 63));
    }
    int* lst = lists[warp];
    int M = 0;
    const unsigned ltmask = (1u << lane) - 1u;
    #pragma unroll
    for (int r = 0; r < 8; r++) {
        const unsigned bal = __ballot_sync(0xffffffffu, av[r]);
        if (av[r]) lst[M + __popc(bal & ltmask)] = pk[r];
        M += __popc(bal);
    }

    // ---- Gaussian sum (warps 0-2 hold t<96) ------------------------------
    float gval = 0.0f;
    if (t < KS) {
        const float a = (float)(t - KS / 2);      // [-46, 46]
        gval = __expf(-(a * a) * inv2s2);
    }
    if (warp < 3) {
        float v = gval;
        #pragma unroll
        for (int off = 16; off > 0; off >>= 1) v += __shfl_down_sync(0xffffffffu, v, off);
        if (lane == 0) wsum[warp] = v;
    }
    __syncthreads();                               // B1: wsum (and lists) ready
    const float invT = 1.0f / (wsum[0] + wsum[1] + wsum[2]);

    // ---- Branch-free table build: one entry per thread (220 < 256) -------
    if (t < GLEN) {
        const int d0 = t - P, d1 = d0 + 1;
        const float a0 = (float)(d0 - KS / 2);
        const float a1 = (float)(d1 - KS / 2);
        const float e0 = __expf(-(a0 * a0) * inv2s2) * invT;
        const float e1 = __expf(-(a1 * a1) * inv2s2) * invT;
        const float g0 = ((unsigned)d0 < (unsigned)KS) ? e0 : 0.0f;
        const float g1 = ((unsigned)d1 < (unsigned)KS) ? e1 : 0.0f;
        gpair[t] = make_float2(g0, g1);
        gquad[t] = make_float4(g0, g0, g1, g1);
    }
    __syncthreads();                               // B2: tables ready (last barrier)

    // ---- Phase 2: packed f32x2, 8 rows x 2 cols per lane per point -------
    uint64_t acc[RPB];
    #pragma unroll
    for (int r = 0; r < RPB; r++) acc[r] = 0ull;
    const char* gq = (const char*)gquad;
    const char* gp = (const char*)gpair + 16 * lane;   // + 2*lane float2s

    #pragma unroll 8
    for (int m = 0; m < M; m++) {
        const int e = lst[m];                      // broadcast LDS.32
        const uint64_t gv2 = *(const uint64_t*)(gp + (e & 0xffff));
        const char* wq = gq + (e >> 16);           // warp-uniform quad base
        const ulonglong2 q0 = *(const ulonglong2*)(wq);
        const ulonglong2 q1 = *(const ulonglong2*)(wq + 32);
        const ulonglong2 q2 = *(const ulonglong2*)(wq + 64);
        const ulonglong2 q3 = *(const ulonglong2*)(wq + 96);
        asm("fma.rn.f32x2 %0, %1, %2, %0;" : "+l"(acc[0]) : "l"(gv2), "l"(q0.x));
        asm("fma.rn.f32x2 %0, %1, %2, %0;" : "+l"(acc[1]) : "l"(gv2), "l"(q0.y));
        asm("fma.rn.f32x2 %0, %1, %2, %0;" : "+l"(acc[2]) : "l"(gv2), "l"(q1.x));
        asm("fma.rn.f32x2 %0, %1, %2, %0;" : "+l"(acc[3]) : "l"(gv2), "l"(q1.y));
        asm("fma.rn.f32x2 %0, %1, %2, %0;" : "+l"(acc[4]) : "l"(gv2), "l"(q2.x));
        asm("fma.rn.f32x2 %0, %1, %2, %0;" : "+l"(acc[5]) : "l"(gv2), "l"(q2.y));
        asm("fma.rn.f32x2 %0, %1, %2, %0;" : "+l"(acc[6]) : "l"(gv2), "l"(q3.x));
        asm("fma.rn.f32x2 %0, %1, %2, %0;" : "+l"(acc[7]) : "l"(gv2), "l"(q3.y));
    }

    // ---- Write 8 rows x 64 cols (2 per lane), STG.64 coalesced ----------
    float* o = out + ((size_t)b * H_OUT + rowBase) * W_OUT + cbw + 2 * lane;
    #pragma unroll
    for (int r = 0; r < RPB; r++) {
        uint32_t lo, hi;
        asm("mov.b64 {%0, %1}, %2;" : "=r"(lo), "=r"(hi) : "l"(acc[r]));
        *(float2*)&o[r * W_OUT] = make_float2(__uint_as_float(lo), __uint_as_float(hi));
    }
}

extern "C" void kernel_launch(void* const* d_in, const int* in_sizes, int n_in,
                              void* d_out, int out_size) {
    // metadata order: [0] batch_images (unused by the math),
    //                 [1] batch_labels [8,256,2] f32, [2] sigma scalar f32
    const float* labels = (const float*)d_in[1];
    const float* sigma  = (const float*)d_in[2];
    float* out = (float*)d_out;                   // [8,1,512,512] f32

    density_kernel<<<8 * (H_OUT / RPB), NT>>>(labels, sigma, out);
}

// round 15
// speedup vs baseline: 1.0563x; 1.0563x over previous
#include <cuda_runtime.h>
#include <cstdint>

#define KS 93          // gaussian kernel size (static, matches reference)
#define NPTS 256       // points per batch
#define W_OUT 512
#define H_OUT 512
#define RPB 8          // rows per warp tile
#define NT 128         // 4 warps per block; warp w -> 64-col window
#define P 64           // gaussian table base: index for patch offset 0
#define GLEN 220       // table length: nonzero exactly in [P, P+93)

// One block per (batch, 8-row group, 256-col half): grid = 8*64*2 = 1024.
// Warp w owns cols [half*256 + 64w, +64); lane owns 2 adjacent columns.
// Classification is warp-local, pre-barrier. Phase 2 is software-pipelined
// (list entry prefetch) with max register budget (occupancy is grid-capped
// at 7 blocks/SM, so up to ~73 regs/thread are free).
__global__ __launch_bounds__(NT, 1)
void density_kernel(const float* __restrict__ labels,
                    const float* __restrict__ sigma_ptr,
                    float* __restrict__ out) {
    const int half    = blockIdx.x & 1;
    const int rowBase = ((blockIdx.x >> 1) & 63) * RPB;
    const int b       = blockIdx.x >> 7;
    const int t    = threadIdx.x;
    const int warp = t >> 5;
    const int lane = t & 31;
    const int cbw  = half * 256 + warp * 64;      // this warp's column base

    __shared__ __align__(16) float4 gquad[GLEN];  // {T[i],T[i],T[i+1],T[i+1]}
    __shared__ __align__(8)  float2 gpair[GLEN];  // {T[i], T[i+1]}
    __shared__ int   lists[4][NPTS + 8];          // warp-private lists (+pad for prefetch)
    __shared__ float wsum[3];

    // ---- Kick off global loads (8 labels per lane + sigma) ---------------
    const float2* lab = (const float2*)(labels + (size_t)b * NPTS * 2);
    float2 pt[8];
    #pragma unroll
    for (int r = 0; r < 8; r++) pt[r] = lab[r * 32 + lane];
    const float s = fabsf(sigma_ptr[0]);
    const float inv2s2 = 1.0f / (2.0f * s * s);

    // ---- Warp-local classification (no table dependency; pre-barrier) ----
    // da7  = rowBase - R0 + 7  in [0, 99]  <-> row window hit
    // dc63 = cbw    - C0 + 63 in [0, 155] <-> col window hit
    int  pk[8];
    bool av[8];
    #pragma unroll
    for (int r = 0; r < 8; r++) {
        const int da7  = rowBase - (int)truncf(pt[r].x - 46.5f) + 7;
        const int dc63 = cbw     - (int)truncf(pt[r].y - 46.5f) + 63;
        pk[r] = (da7 << 8) | dc63;
        av[r] = ((unsigned)da7  < (unsigned)(KS + RPB - 1)) &&
                ((unsigned)dc63 < (unsigned)(KS + 63));
    }
    int* lst = lists[warp];
    int M = 0;
    const unsigned ltmask = (1u << lane) - 1u;
    #pragma unroll
    for (int r = 0; r < 8; r++) {
        const unsigned bal = __ballot_sync(0xffffffffu, av[r]);
        if (av[r]) lst[M + __popc(bal & ltmask)] = pk[r];
        M += __popc(bal);
    }
    if (lane == 0) lst[M] = 0;                     // safe prefetch sentinel
    __syncwarp();

    // ---- Gaussian sum (warps 0-2 hold t<96) ------------------------------
    float gval = 0.0f;
    if (t < KS) {
        const float a = (float)(t - KS / 2);      // [-46, 46]
        gval = __expf(-(a * a) * inv2s2);
    }
    if (warp < 3) {
        float v = gval;
        #pragma unroll
        for (int off = 16; off > 0; off >>= 1) v += __shfl_down_sync(0xffffffffu, v, off);
        if (lane == 0) wsum[warp] = v;
    }
    __syncthreads();                               // B1: wsum (and lists) ready
    const float invT = 1.0f / (wsum[0] + wsum[1] + wsum[2]);

    // ---- Branch-free table build: T[i] = norm gaussian at offset i-P -----
    #pragma unroll
    for (int i = t; i < GLEN; i += NT) {
        const int d0 = i - P, d1 = d0 + 1;
        const float a0 = (float)(d0 - KS / 2);
        const float a1 = (float)(d1 - KS / 2);
        const float e0 = __expf(-(a0 * a0) * inv2s2) * invT;
        const float e1 = __expf(-(a1 * a1) * inv2s2) * invT;
        const float g0 = ((unsigned)d0 < (unsigned)KS) ? e0 : 0.0f;
        const float g1 = ((unsigned)d1 < (unsigned)KS) ? e1 : 0.0f;
        gpair[i] = make_float2(g0, g1);
        gquad[i] = make_float4(g0, g0, g1, g1);
    }
    __syncthreads();                               // B2: tables ready (last barrier)

    // ---- Phase 2: pipelined packed f32x2 accumulation --------------------
    uint64_t acc[RPB];
    #pragma unroll
    for (int r = 0; r < RPB; r++) acc[r] = 0ull;
    const int lane2 = 2 * lane;

    int e = lst[0];                                // stage-0 prefetch
    #pragma unroll 8
    for (int m = 0; m < M; m++) {
        const int cur = e;
        e = lst[m + 1];                            // prefetch next entry
        const int da7  = cur >> 8;
        const int dc63 = cur & 255;
        const uint64_t gv2 = *(const uint64_t*)&gpair[1 + dc63 + lane2];
        const float4* wq = &gquad[57 + da7];       // index P-7+da7, warp-uniform
        const ulonglong2 q0 = *(const ulonglong2*)&wq[0];
        const ulonglong2 q1 = *(const ulonglong2*)&wq[2];
        const ulonglong2 q2 = *(const ulonglong2*)&wq[4];
        const ulonglong2 q3 = *(const ulonglong2*)&wq[6];
        asm("fma.rn.f32x2 %0, %1, %2, %0;" : "+l"(acc[0]) : "l"(gv2), "l"(q0.x));
        asm("fma.rn.f32x2 %0, %1, %2, %0;" : "+l"(acc[1]) : "l"(gv2), "l"(q0.y));
        asm("fma.rn.f32x2 %0, %1, %2, %0;" : "+l"(acc[2]) : "l"(gv2), "l"(q1.x));
        asm("fma.rn.f32x2 %0, %1, %2, %0;" : "+l"(acc[3]) : "l"(gv2), "l"(q1.y));
        asm("fma.rn.f32x2 %0, %1, %2, %0;" : "+l"(acc[4]) : "l"(gv2), "l"(q2.x));
        asm("fma.rn.f32x2 %0, %1, %2, %0;" : "+l"(acc[5]) : "l"(gv2), "l"(q2.y));
        asm("fma.rn.f32x2 %0, %1, %2, %0;" : "+l"(acc[6]) : "l"(gv2), "l"(q3.x));
        asm("fma.rn.f32x2 %0, %1, %2, %0;" : "+l"(acc[7]) : "l"(gv2), "l"(q3.y));
    }

    // ---- Write 8 rows x 64 cols (2 per lane), STG.64 coalesced ----------
    float* o = out + ((size_t)b * H_OUT + rowBase) * W_OUT + cbw + lane2;
    #pragma unroll
    for (int r = 0; r < RPB; r++) {
        uint32_t lo, hi;
        asm("mov.b64 {%0, %1}, %2;" : "=r"(lo), "=r"(hi) : "l"(acc[r]));
        *(float2*)&o[r * W_OUT] = make_float2(__uint_as_float(lo), __uint_as_float(hi));
    }
}

extern "C" void kernel_launch(void* const* d_in, const int* in_sizes, int n_in,
                              void* d_out, int out_size) {
    // metadata order: [0] batch_images (unused by the math),
    //                 [1] batch_labels [8,256,2] f32, [2] sigma scalar f32
    const float* labels = (const float*)d_in[1];
    const float* sigma  = (const float*)d_in[2];
    float* out = (float*)d_out;                   // [8,1,512,512] f32

    density_kernel<<<8 * (H_OUT / RPB) * 2, NT>>>(labels, sigma, out);
}